// round 3
// baseline (speedup 1.0000x reference)
#include <cuda_runtime.h>
#include <cuda_bf16.h>
#include <math.h>

#define FULL 0xffffffffu
#define MAXNR 131072
#define NBINS 257   // lengths 0..256

typedef unsigned long long ull;

// Scratch (device globals; no allocation allowed)
__device__ float g_emb[MAXNR * 32];
__device__ int   g_hist[NBINS];
__device__ int   g_binbase[NBINS];
__device__ int   g_perm[MAXNR];

// ---------------------------------------------------------------------------
// f32x2 packed helpers (Blackwell FFMA2 path — only reachable via PTX)
// ---------------------------------------------------------------------------
__device__ __forceinline__ ull pack2(float lo, float hi) {
    ull r; asm("mov.b64 %0, {%1, %2};" : "=l"(r) : "f"(lo), "f"(hi)); return r;
}
__device__ __forceinline__ void unpack2(ull v, float& lo, float& hi) {
    asm("mov.b64 {%0, %1}, %2;" : "=f"(lo), "=f"(hi) : "l"(v));
}
__device__ __forceinline__ ull fma2(ull a, ull b, ull c) {
    ull d; asm("fma.rn.f32x2 %0, %1, %2, %3;" : "=l"(d) : "l"(a), "l"(b), "l"(c)); return d;
}
__device__ __forceinline__ float ex2f(float x) {
    float r; asm("ex2.approx.f32 %0, %1;" : "=f"(r) : "f"(x)); return r;
}
__device__ __forceinline__ float rcpf(float x) {
    float r; asm("rcp.approx.f32 %0, %1;" : "=f"(r) : "f"(x)); return r;
}

// ---------------------------------------------------------------------------
// Counting sort by length (descending), with per-block aggregated scatter.
// ---------------------------------------------------------------------------
__global__ void zero_hist_kernel() {
    int i = threadIdx.x;
    if (i < NBINS) g_hist[i] = 0;
}

__global__ void hist_kernel(const int* __restrict__ l, int NR) {
    __shared__ int sh[NBINS];
    for (int i = threadIdx.x; i < NBINS; i += blockDim.x) sh[i] = 0;
    __syncthreads();
    int i = blockIdx.x * blockDim.x + threadIdx.x;
    if (i < NR) atomicAdd(&sh[l[i]], 1);
    __syncthreads();
    for (int i2 = threadIdx.x; i2 < NBINS; i2 += blockDim.x)
        if (sh[i2]) atomicAdd(&g_hist[i2], sh[i2]);
}

// Exclusive suffix-sum -> bin bases (longer lengths first).
__global__ void scan_kernel() {   // 1 block, 512 threads
    __shared__ int s[512];
    int tid = threadIdx.x;
    int hv = (tid < NBINS) ? g_hist[256 - tid] : 0;
    s[tid] = hv;
    __syncthreads();
    for (int off = 1; off < 512; off <<= 1) {
        int v = (tid >= off) ? s[tid - off] : 0;
        __syncthreads();
        s[tid] += v;
        __syncthreads();
    }
    if (tid < NBINS) g_binbase[256 - tid] = s[tid] - hv;
}

__global__ void scatter_kernel(const int* __restrict__ l, int NR) {
    __shared__ int scount[NBINS];   // per-block counts
    __shared__ int sbase[NBINS];    // this block's reserved base per bin
    for (int i = threadIdx.x; i < NBINS; i += blockDim.x) scount[i] = 0;
    __syncthreads();
    int i = blockIdx.x * blockDim.x + threadIdx.x;
    int len = 0, local = 0;
    if (i < NR) {
        len = l[i];
        local = atomicAdd(&scount[len], 1);   // rank within block
    }
    __syncthreads();
    for (int b = threadIdx.x; b < NBINS; b += blockDim.x)
        sbase[b] = scount[b] ? atomicAdd(&g_binbase[b], scount[b]) : 0;
    __syncthreads();
    if (i < NR) g_perm[sbase[len] + local] = i;
}

// ---------------------------------------------------------------------------
// RNN: lane-per-sequence, f32x2 packed math.
// Weights packed by output pairs: sWp[m*32+j] = (W_hh[2m][j], W_hh[2m+1][j]).
// Per step: acc_m = bias_m + (x,x)*wih_m + sum_j sWp[m][j] * (h_j, h_j).
// ---------------------------------------------------------------------------
__global__ __launch_bounds__(256) void rnn_kernel(
    const float* __restrict__ h,
    const int*   __restrict__ l,
    const float* __restrict__ W_ih,
    const float* __restrict__ W_hh,
    const float* __restrict__ b_ih,
    const float* __restrict__ b_hh,
    int NR, int T)
{
    __shared__ ull sWp[16 * 32];
    __shared__ ull swihp[16];
    __shared__ ull sbiasp[16];

    int tid = threadIdx.x;
    // pack weights: sWp[m*32+j] = (W[2m][j], W[2m+1][j])
    for (int idx = tid; idx < 16 * 32; idx += blockDim.x) {
        int m = idx >> 5, j = idx & 31;
        sWp[idx] = pack2(W_hh[(2 * m) * 32 + j], W_hh[(2 * m + 1) * 32 + j]);
    }
    if (tid < 16) {
        swihp[tid]  = pack2(W_ih[2 * tid], W_ih[2 * tid + 1]);
        sbiasp[tid] = pack2(b_ih[2 * tid] + b_hh[2 * tid],
                            b_ih[2 * tid + 1] + b_hh[2 * tid + 1]);
    }
    __syncthreads();

    int lane = tid & 31;
    int gi   = (blockIdx.x * blockDim.x + tid);   // sorted index (lane-per-seq)
    int seq  = (gi < NR) ? g_perm[gi] : 0;
    int len  = (gi < NR) ? l[seq] : 0;
    const float* hp = h + (size_t)seq * T;

    float hs[32];            // scalar hidden state
    ull   hjj[32];           // (h_j, h_j) packed broadcasts
#pragma unroll
    for (int j = 0; j < 32; j++) { hs[j] = 0.0f; hjj[j] = pack2(0.0f, 0.0f); }

    int maxlen = __reduce_max_sync(FULL, len);

    const float C2L2E = 2.8853900817779268f;   // 2 * log2(e)

    float xn = (len > 0) ? __ldg(hp + (len - 1)) : 0.0f;

    for (int t = 0; t < maxlen; t++) {
        float x = xn;
        int p = len - 2 - t;
        xn = __ldg(hp + (p > 0 ? p : 0));
        bool live = t < len;
        ull xx = pack2(x, x);

#pragma unroll 2
        for (int m = 0; m < 16; m++) {
            ull acc0 = fma2(swihp[m], xx, sbiasp[m]);
            ull acc1 = pack2(0.0f, 0.0f);
#pragma unroll
            for (int j = 0; j < 32; j += 2) {
                acc0 = fma2(sWp[m * 32 + j],     hjj[j],     acc0);
                acc1 = fma2(sWp[m * 32 + j + 1], hjj[j + 1], acc1);
            }
            float a0, a1, e0h, e1h;
            unpack2(acc0, a0, a1);
            unpack2(acc1, e0h, e1h);
            a0 += e0h; a1 += e1h;
            // tanh(a) = 1 - 2/(exp(2a)+1) = 1 - 2*rcp(ex2(a*2log2e)+1)
            float e0 = ex2f(a0 * C2L2E);
            float e1 = ex2f(a1 * C2L2E);
            float r0 = rcpf(e0 + 1.0f);
            float r1 = rcpf(e1 + 1.0f);
            float n0 = fmaf(-2.0f, r0, 1.0f);
            float n1 = fmaf(-2.0f, r1, 1.0f);
            hs[2 * m]     = live ? n0 : hs[2 * m];
            hs[2 * m + 1] = live ? n1 : hs[2 * m + 1];
        }
#pragma unroll
        for (int j = 0; j < 32; j++) hjj[j] = pack2(hs[j], hs[j]);
    }

    // Transposed coalesced store via shared
    __shared__ float sout[256 * 33 / 32];   // 8 warps * 32*33 floats? too big -> per-warp reuse
    // (use warp-local region: 32*33 floats per warp would be 33KB; instead
    //  write directly — gathers, but only 16MB total once)
    if (gi < NR) {
#pragma unroll
        for (int j = 0; j < 32; j++) g_emb[(size_t)seq * 32 + j] = hs[j];
    }
    (void)sout; (void)lane;
}

// ---------------------------------------------------------------------------
// MLP head: warp-per-sample.
// ---------------------------------------------------------------------------
__global__ __launch_bounds__(256) void mlp_kernel(
    const float* __restrict__ W1, const float* __restrict__ b1,
    const float* __restrict__ W2, const float* __restrict__ b2,
    const float* __restrict__ W3, const float* __restrict__ b3,
    float* __restrict__ out, int N, int R)
{
    __shared__ float W1s[128 * 32];
    __shared__ float W2s[32 * 32];
    __shared__ float W3s[32 * 8];
    __shared__ float b1s[32], b2s[32], b3s[8];

    int tid = threadIdx.x;
    int RH  = R * 32;
    for (int i = tid; i < RH * 32; i += blockDim.x) W1s[i] = W1[i];
    for (int i = tid; i < 32 * 32; i += blockDim.x) W2s[i] = W2[i];
    for (int i = tid; i < 32 * R;  i += blockDim.x) W3s[i] = W3[i];
    if (tid < 32) { b1s[tid] = b1[tid]; b2s[tid] = b2[tid]; }
    if (tid < R)  b3s[tid] = b3[tid];
    __syncthreads();

    int warp = (int)((blockIdx.x * blockDim.x + tid) >> 5);
    int lane = tid & 31;
    if (warp >= N) return;

    float f0 = g_emb[((size_t)warp * R + 0) * 32 + lane];
    float f1 = g_emb[((size_t)warp * R + 1) * 32 + lane];
    float f2 = g_emb[((size_t)warp * R + 2) * 32 + lane];
    float f3 = g_emb[((size_t)warp * R + 3) * 32 + lane];

    float z = b1s[lane];
#pragma unroll
    for (int m = 0; m < 32; m++) {
        float fm = __shfl_sync(FULL, f0, m);
        z = fmaf(fm, W1s[m * 32 + lane], z);
    }
#pragma unroll
    for (int m = 0; m < 32; m++) {
        float fm = __shfl_sync(FULL, f1, m);
        z = fmaf(fm, W1s[(32 + m) * 32 + lane], z);
    }
#pragma unroll
    for (int m = 0; m < 32; m++) {
        float fm = __shfl_sync(FULL, f2, m);
        z = fmaf(fm, W1s[(64 + m) * 32 + lane], z);
    }
#pragma unroll
    for (int m = 0; m < 32; m++) {
        float fm = __shfl_sync(FULL, f3, m);
        z = fmaf(fm, W1s[(96 + m) * 32 + lane], z);
    }
    z = fmaxf(z, 0.0f);

    float z2 = b2s[lane];
#pragma unroll
    for (int m = 0; m < 32; m++) {
        float zm = __shfl_sync(FULL, z, m);
        z2 = fmaf(zm, W2s[m * 32 + lane], z2);
    }
    z2 = fmaxf(z2, 0.0f);

    for (int c = 0; c < R; c++) {
        float v = z2 * W3s[lane * R + c];
#pragma unroll
        for (int off = 16; off; off >>= 1) v += __shfl_xor_sync(FULL, v, off);
        if (lane == 0) out[(size_t)warp * R + c] = v + b3s[c];
    }
}

// ---------------------------------------------------------------------------
// Launcher. Inputs: h, l, W_ih, W_hh, b_ih, b_hh, W1, b1, W2, b2, W3, b3
// ---------------------------------------------------------------------------
extern "C" void kernel_launch(void* const* d_in, const int* in_sizes, int n_in,
                              void* d_out, int out_size)
{
    const float* h    = (const float*)d_in[0];
    const int*   l    = (const int*)  d_in[1];
    const float* W_ih = (const float*)d_in[2];
    const float* W_hh = (const float*)d_in[3];
    const float* b_ih = (const float*)d_in[4];
    const float* b_hh = (const float*)d_in[5];
    const float* W1   = (const float*)d_in[6];
    const float* b1   = (const float*)d_in[7];
    const float* W2   = (const float*)d_in[8];
    const float* b2   = (const float*)d_in[9];
    const float* W3   = (const float*)d_in[10];
    const float* b3   = (const float*)d_in[11];
    float* out = (float*)d_out;

    int NR = in_sizes[1];
    int T  = in_sizes[0] / NR;
    int R  = in_sizes[10] / 32;
    int N  = NR / R;

    zero_hist_kernel<<<1, 512>>>();
    hist_kernel<<<(NR + 255) / 256, 256>>>(l, NR);
    scan_kernel<<<1, 512>>>();
    scatter_kernel<<<(NR + 255) / 256, 256>>>(l, NR);

    rnn_kernel<<<(NR + 255) / 256, 256>>>(h, l, W_ih, W_hh, b_ih, b_hh, NR, T);

    mlp_kernel<<<(N + 7) / 8, 256>>>(W1, b1, W2, b2, W3, b3, out, N, R);
}

// round 4
// speedup vs baseline: 1.1309x; 1.1309x over previous
#include <cuda_runtime.h>
#include <cuda_bf16.h>
#include <math.h>

#define FULL 0xffffffffu
#define MAXNR 131072
#define NBINS 257   // lengths 0..256

typedef unsigned long long ull;

// Scratch (device globals; no allocation allowed)
__device__ float g_emb[MAXNR * 32];
__device__ int   g_hist[NBINS];
__device__ int   g_binbase[NBINS];
__device__ int   g_perm[MAXNR];

// ---------------------------------------------------------------------------
// f32x2 packed helpers (Blackwell FFMA2 path — only reachable via PTX)
// ---------------------------------------------------------------------------
__device__ __forceinline__ ull pack2(float lo, float hi) {
    ull r; asm("mov.b64 %0, {%1, %2};" : "=l"(r) : "f"(lo), "f"(hi)); return r;
}
__device__ __forceinline__ void unpack2(ull v, float& lo, float& hi) {
    asm("mov.b64 {%0, %1}, %2;" : "=f"(lo), "=f"(hi) : "l"(v));
}
__device__ __forceinline__ ull fma2(ull a, ull b, ull c) {
    ull d; asm("fma.rn.f32x2 %0, %1, %2, %3;" : "=l"(d) : "l"(a), "l"(b), "l"(c)); return d;
}
__device__ __forceinline__ ull add2(ull a, ull b) {
    ull d; asm("add.rn.f32x2 %0, %1, %2;" : "=l"(d) : "l"(a), "l"(b)); return d;
}
__device__ __forceinline__ void lds_v2u64(ull& a, ull& b, const ull* p) {
    asm("ld.shared.v2.u64 {%0, %1}, [%2];"
        : "=l"(a), "=l"(b) : "l"(__cvta_generic_to_shared(p)));
}
__device__ __forceinline__ float ex2f(float x) {
    float r; asm("ex2.approx.f32 %0, %1;" : "=f"(r) : "f"(x)); return r;
}
__device__ __forceinline__ float rcpf(float x) {
    float r; asm("rcp.approx.f32 %0, %1;" : "=f"(r) : "f"(x)); return r;
}

// ---------------------------------------------------------------------------
// Counting sort by length (descending), per-block aggregated scatter.
// ---------------------------------------------------------------------------
__global__ void zero_hist_kernel() {
    int i = threadIdx.x;
    if (i < NBINS) g_hist[i] = 0;
}

__global__ void hist_kernel(const int* __restrict__ l, int NR) {
    __shared__ int sh[NBINS];
    for (int i = threadIdx.x; i < NBINS; i += blockDim.x) sh[i] = 0;
    __syncthreads();
    int i = blockIdx.x * blockDim.x + threadIdx.x;
    if (i < NR) atomicAdd(&sh[l[i]], 1);
    __syncthreads();
    for (int i2 = threadIdx.x; i2 < NBINS; i2 += blockDim.x)
        if (sh[i2]) atomicAdd(&g_hist[i2], sh[i2]);
}

__global__ void scan_kernel() {   // 1 block, 512 threads
    __shared__ int s[512];
    int tid = threadIdx.x;
    int hv = (tid < NBINS) ? g_hist[256 - tid] : 0;
    s[tid] = hv;
    __syncthreads();
    for (int off = 1; off < 512; off <<= 1) {
        int v = (tid >= off) ? s[tid - off] : 0;
        __syncthreads();
        s[tid] += v;
        __syncthreads();
    }
    if (tid < NBINS) g_binbase[256 - tid] = s[tid] - hv;
}

__global__ void scatter_kernel(const int* __restrict__ l, int NR) {
    __shared__ int scount[NBINS];
    __shared__ int sbase[NBINS];
    for (int i = threadIdx.x; i < NBINS; i += blockDim.x) scount[i] = 0;
    __syncthreads();
    int i = blockIdx.x * blockDim.x + threadIdx.x;
    int len = 0, local = 0;
    if (i < NR) {
        len = l[i];
        local = atomicAdd(&scount[len], 1);
    }
    __syncthreads();
    for (int b = threadIdx.x; b < NBINS; b += blockDim.x)
        sbase[b] = scount[b] ? atomicAdd(&g_binbase[b], scount[b]) : 0;
    __syncthreads();
    if (i < NR) g_perm[sbase[len] + local] = i;
}

// ---------------------------------------------------------------------------
// RNN: lane-per-sequence, f32x2 packed over j-pairs (register-lean).
//   hpack[jj] = (h_{2jj}, h_{2jj+1})                          [16 ull, 32 regs]
//   sW2[m*16+jj] = s*(W_hh[m][2jj], W_hh[m][2jj+1])           [shared, LDS.128]
//   swihb[m] = s*(W_ih[m], b_ih[m]+b_hh[m])                   [shared]
//   s = 2*log2(e) folded into weights so tanh = 1 - 2*rcp(ex2(a)+1).
// ---------------------------------------------------------------------------
__global__ __launch_bounds__(256) void rnn_kernel(
    const float* __restrict__ h,
    const int*   __restrict__ l,
    const float* __restrict__ W_ih,
    const float* __restrict__ W_hh,
    const float* __restrict__ b_ih,
    const float* __restrict__ b_hh,
    int NR, int T)
{
    __shared__ ull sW2[32 * 16];   // 4KB
    __shared__ ull swihb[32];

    const float S = 2.8853900817779268f;   // 2*log2(e)
    int tid = threadIdx.x;
    for (int idx = tid; idx < 32 * 16; idx += blockDim.x) {
        int m = idx >> 4, jj = idx & 15;
        sW2[idx] = pack2(S * W_hh[m * 32 + 2 * jj], S * W_hh[m * 32 + 2 * jj + 1]);
    }
    if (tid < 32)
        swihb[tid] = pack2(S * W_ih[tid], S * (b_ih[tid] + b_hh[tid]));
    __syncthreads();

    int gi  = blockIdx.x * blockDim.x + tid;   // sorted index
    int seq = (gi < NR) ? g_perm[gi] : 0;
    int len = (gi < NR) ? l[seq] : 0;
    const float* hp = h + (size_t)seq * T;

    ull hpack[16];
#pragma unroll
    for (int jj = 0; jj < 16; jj++) hpack[jj] = 0ULL;

    int maxlen = __reduce_max_sync(FULL, len);

    float xn = (len > 0) ? __ldg(hp + (len - 1)) : 0.0f;

    for (int t = 0; t < maxlen; t++) {
        float x = xn;
        int p = len - 2 - t;
        xn = __ldg(hp + (p > 0 ? p : 0));
        bool live = t < len;
        ull xb = pack2(x, 1.0f);

        // Phase 1: all 32 pre-activations (reads hpack, writes a[])
        float a[32];
#pragma unroll
        for (int m = 0; m < 32; m++) {
            ull acc0 = fma2(swihb[m], xb, 0ULL);   // lo=s*wih*x, hi=s*bias
            ull acc1 = 0ULL;
#pragma unroll
            for (int q = 0; q < 8; q++) {
                ull wA, wB;
                lds_v2u64(wA, wB, &sW2[m * 16 + 2 * q]);
                acc0 = fma2(wA, hpack[2 * q],     acc0);
                acc1 = fma2(wB, hpack[2 * q + 1], acc1);
            }
            ull accs = add2(acc0, acc1);
            float lo, hi;
            unpack2(accs, lo, hi);
            a[m] = lo + hi;
        }

        // Phase 2: tanh + repack in place
#pragma unroll
        for (int m2 = 0; m2 < 16; m2++) {
            float e0 = ex2f(a[2 * m2]);
            float e1 = ex2f(a[2 * m2 + 1]);
            float r0 = rcpf(e0 + 1.0f);
            float r1 = rcpf(e1 + 1.0f);
            float n0 = fmaf(-2.0f, r0, 1.0f);
            float n1 = fmaf(-2.0f, r1, 1.0f);
            ull nv = pack2(n0, n1);
            hpack[m2] = live ? nv : hpack[m2];
        }
    }

    if (gi < NR) {
        float4* gout = reinterpret_cast<float4*>(&g_emb[(size_t)seq * 32]);
#pragma unroll
        for (int q = 0; q < 8; q++) {
            float lo0, hi0, lo1, hi1;
            unpack2(hpack[2 * q],     lo0, hi0);
            unpack2(hpack[2 * q + 1], lo1, hi1);
            gout[q] = make_float4(lo0, hi0, lo1, hi1);
        }
    }
}

// ---------------------------------------------------------------------------
// MLP head: warp-per-sample.
// ---------------------------------------------------------------------------
__global__ __launch_bounds__(256) void mlp_kernel(
    const float* __restrict__ W1, const float* __restrict__ b1,
    const float* __restrict__ W2, const float* __restrict__ b2,
    const float* __restrict__ W3, const float* __restrict__ b3,
    float* __restrict__ out, int N, int R)
{
    __shared__ float W1s[128 * 32];
    __shared__ float W2s[32 * 32];
    __shared__ float W3s[32 * 8];
    __shared__ float b1s[32], b2s[32], b3s[8];

    int tid = threadIdx.x;
    int RH  = R * 32;
    for (int i = tid; i < RH * 32; i += blockDim.x) W1s[i] = W1[i];
    for (int i = tid; i < 32 * 32; i += blockDim.x) W2s[i] = W2[i];
    for (int i = tid; i < 32 * R;  i += blockDim.x) W3s[i] = W3[i];
    if (tid < 32) { b1s[tid] = b1[tid]; b2s[tid] = b2[tid]; }
    if (tid < R)  b3s[tid] = b3[tid];
    __syncthreads();

    int warp = (int)((blockIdx.x * blockDim.x + tid) >> 5);
    int lane = tid & 31;
    if (warp >= N) return;

    float f0 = g_emb[((size_t)warp * R + 0) * 32 + lane];
    float f1 = g_emb[((size_t)warp * R + 1) * 32 + lane];
    float f2 = g_emb[((size_t)warp * R + 2) * 32 + lane];
    float f3 = g_emb[((size_t)warp * R + 3) * 32 + lane];

    float z = b1s[lane];
#pragma unroll
    for (int m = 0; m < 32; m++) {
        float fm = __shfl_sync(FULL, f0, m);
        z = fmaf(fm, W1s[m * 32 + lane], z);
    }
#pragma unroll
    for (int m = 0; m < 32; m++) {
        float fm = __shfl_sync(FULL, f1, m);
        z = fmaf(fm, W1s[(32 + m) * 32 + lane], z);
    }
#pragma unroll
    for (int m = 0; m < 32; m++) {
        float fm = __shfl_sync(FULL, f2, m);
        z = fmaf(fm, W1s[(64 + m) * 32 + lane], z);
    }
#pragma unroll
    for (int m = 0; m < 32; m++) {
        float fm = __shfl_sync(FULL, f3, m);
        z = fmaf(fm, W1s[(96 + m) * 32 + lane], z);
    }
    z = fmaxf(z, 0.0f);

    float z2 = b2s[lane];
#pragma unroll
    for (int m = 0; m < 32; m++) {
        float zm = __shfl_sync(FULL, z, m);
        z2 = fmaf(zm, W2s[m * 32 + lane], z2);
    }
    z2 = fmaxf(z2, 0.0f);

    for (int c = 0; c < R; c++) {
        float v = z2 * W3s[lane * R + c];
#pragma unroll
        for (int off = 16; off; off >>= 1) v += __shfl_xor_sync(FULL, v, off);
        if (lane == 0) out[(size_t)warp * R + c] = v + b3s[c];
    }
}

// ---------------------------------------------------------------------------
// Launcher. Inputs: h, l, W_ih, W_hh, b_ih, b_hh, W1, b1, W2, b2, W3, b3
// ---------------------------------------------------------------------------
extern "C" void kernel_launch(void* const* d_in, const int* in_sizes, int n_in,
                              void* d_out, int out_size)
{
    const float* h    = (const float*)d_in[0];
    const int*   l    = (const int*)  d_in[1];
    const float* W_ih = (const float*)d_in[2];
    const float* W_hh = (const float*)d_in[3];
    const float* b_ih = (const float*)d_in[4];
    const float* b_hh = (const float*)d_in[5];
    const float* W1   = (const float*)d_in[6];
    const float* b1   = (const float*)d_in[7];
    const float* W2   = (const float*)d_in[8];
    const float* b2   = (const float*)d_in[9];
    const float* W3   = (const float*)d_in[10];
    const float* b3   = (const float*)d_in[11];
    float* out = (float*)d_out;

    int NR = in_sizes[1];
    int T  = in_sizes[0] / NR;
    int R  = in_sizes[10] / 32;
    int N  = NR / R;

    zero_hist_kernel<<<1, 512>>>();
    hist_kernel<<<(NR + 255) / 256, 256>>>(l, NR);
    scan_kernel<<<1, 512>>>();
    scatter_kernel<<<(NR + 255) / 256, 256>>>(l, NR);

    rnn_kernel<<<(NR + 255) / 256, 256>>>(h, l, W_ih, W_hh, b_ih, b_hh, NR, T);

    mlp_kernel<<<(N + 7) / 8, 256>>>(W1, b1, W2, b2, W3, b3, out, N, R);
}

// round 5
// speedup vs baseline: 2.0424x; 1.8060x over previous
#include <cuda_runtime.h>
#include <cuda_bf16.h>
#include <math.h>

#define FULL 0xffffffffu
#define MAXNR 131072
#define NBINS 257

typedef unsigned int uint;

// Scratch (device globals; no allocation allowed)
__device__ float g_emb[MAXNR * 32];
__device__ int   g_hist[NBINS];
__device__ int   g_binbase[NBINS];
__device__ int   g_perm[MAXNR];

// ---------------------------------------------------------------------------
// helpers
// ---------------------------------------------------------------------------
__device__ __forceinline__ float ex2f(float x) {
    float r; asm("ex2.approx.f32 %0, %1;" : "=f"(r) : "f"(x)); return r;
}
__device__ __forceinline__ float rcpf(float x) {
    float r; asm("rcp.approx.f32 %0, %1;" : "=f"(r) : "f"(x)); return r;
}
__device__ __forceinline__ float trunc13(float x) {   // tf32 truncation split
    return __uint_as_float(__float_as_uint(x) & 0xFFFFE000u);
}
__device__ __forceinline__ void mma_tf32(
    float& d0, float& d1, float& d2, float& d3,
    uint a0, uint a1, uint a2, uint a3, uint b0, uint b1)
{
    asm("mma.sync.aligned.m16n8k8.row.col.f32.tf32.tf32.f32 "
        "{%0,%1,%2,%3}, {%4,%5,%6,%7}, {%8,%9}, {%0,%1,%2,%3};"
        : "+f"(d0), "+f"(d1), "+f"(d2), "+f"(d3)
        : "r"(a0), "r"(a1), "r"(a2), "r"(a3), "r"(b0), "r"(b1));
}

// ---------------------------------------------------------------------------
// Counting sort by length (descending)
// ---------------------------------------------------------------------------
__global__ void zero_hist_kernel() {
    int i = threadIdx.x;
    if (i < NBINS) g_hist[i] = 0;
}

__global__ void hist_kernel(const int* __restrict__ l, int NR) {
    __shared__ int sh[NBINS];
    for (int i = threadIdx.x; i < NBINS; i += blockDim.x) sh[i] = 0;
    __syncthreads();
    int i = blockIdx.x * blockDim.x + threadIdx.x;
    if (i < NR) atomicAdd(&sh[l[i]], 1);
    __syncthreads();
    for (int i2 = threadIdx.x; i2 < NBINS; i2 += blockDim.x)
        if (sh[i2]) atomicAdd(&g_hist[i2], sh[i2]);
}

__global__ void scan_kernel() {   // 1 block, 512 threads
    __shared__ int s[512];
    int tid = threadIdx.x;
    int hv = (tid < NBINS) ? g_hist[256 - tid] : 0;
    s[tid] = hv;
    __syncthreads();
    for (int off = 1; off < 512; off <<= 1) {
        int v = (tid >= off) ? s[tid - off] : 0;
        __syncthreads();
        s[tid] += v;
        __syncthreads();
    }
    if (tid < NBINS) g_binbase[256 - tid] = s[tid] - hv;
}

__global__ void scatter_kernel(const int* __restrict__ l, int NR) {
    __shared__ int scount[NBINS];
    __shared__ int sbase[NBINS];
    for (int i = threadIdx.x; i < NBINS; i += blockDim.x) scount[i] = 0;
    __syncthreads();
    int i = blockIdx.x * blockDim.x + threadIdx.x;
    int len = 0, local = 0;
    if (i < NR) {
        len = l[i];
        local = atomicAdd(&scount[len], 1);
    }
    __syncthreads();
    for (int b = threadIdx.x; b < NBINS; b += blockDim.x)
        sbase[b] = scount[b] ? atomicAdd(&g_binbase[b], scount[b]) : 0;
    __syncthreads();
    if (i < NR) g_perm[sbase[len] + local] = i;
}

// ---------------------------------------------------------------------------
// RNN via tensor cores (mma.sync tf32, 3xTF32 precision).
// Per warp: 32 sorted sequences. Per step: a = S*(W@H + wih*x + b) as a
// 32x32x32 GEMM (M=i, N=s, K=j), then h = 1 - 2*rcp(ex2(a)+1).
// S = 2*log2(e) pre-folded into W, wih, b.
// ---------------------------------------------------------------------------
#define NW 4   // warps per block

__global__ __launch_bounds__(32 * NW) void rnn_kernel(
    const float* __restrict__ h,
    const int*   __restrict__ l,
    const float* __restrict__ W_ih,
    const float* __restrict__ W_hh,
    const float* __restrict__ b_ih,
    const float* __restrict__ b_hh,
    int NR, int T)
{
    __shared__ float sWhi[32][36];
    __shared__ float sWlo[32][36];
    __shared__ float swihS[32];
    __shared__ float sbS[32];
    __shared__ float Hs[NW][32][36];   // hidden state [j][s]
    __shared__ float sx[NW][32][33];   // staged inputs [t&31][s]

    const float S = 2.8853900817779268f;   // 2*log2(e)
    int tid  = threadIdx.x;
    int w    = tid >> 5;
    int lane = tid & 31;

    // block prep: scaled + split weights
    for (int idx = tid; idx < 1024; idx += 32 * NW) {
        float ws  = S * W_hh[idx];
        float whi = trunc13(ws);
        sWhi[idx >> 5][idx & 31] = whi;
        sWlo[idx >> 5][idx & 31] = ws - whi;
    }
    if (tid < 32) {
        swihS[tid] = S * W_ih[tid];
        sbS[tid]   = S * (b_ih[tid] + b_hh[tid]);
    }
    __syncthreads();

    int gi  = (blockIdx.x * NW + w) * 32 + lane;
    int seq = (gi < NR) ? g_perm[gi] : 0;
    int len = (gi < NR) ? l[seq] : 0;
    int maxlen = __reduce_max_sync(FULL, len);

    int gid = lane >> 2;
    int tig = lane & 3;

#pragma unroll
    for (int j = 0; j < 32; j++) Hs[w][j][lane] = 0.0f;

    uint awhi[2][4][4];
#pragma unroll
    for (int m = 0; m < 2; m++)
#pragma unroll
        for (int k = 0; k < 4; k++) {
            int r0 = 16 * m + gid, r1 = r0 + 8;
            int c0 = 8 * k + tig,  c1 = c0 + 4;
            awhi[m][k][0] = __float_as_uint(sWhi[r0][c0]);
            awhi[m][k][1] = __float_as_uint(sWhi[r1][c0]);
            awhi[m][k][2] = __float_as_uint(sWhi[r0][c1]);
            awhi[m][k][3] = __float_as_uint(sWhi[r1][c1]);
        }

    float wih4[4], b4[4];
#pragma unroll
    for (int q = 0; q < 4; q++) {
        wih4[q] = swihS[gid + 8 * q];
        b4[q]   = sbS[gid + 8 * q];
    }

    int lencol[4][2];
#pragma unroll
    for (int n = 0; n < 4; n++)
#pragma unroll
        for (int u = 0; u < 2; u++)
            lencol[n][u] = __shfl_sync(FULL, len, 8 * n + 2 * tig + u);

    __syncwarp();

    for (int t = 0; t < maxlen; t++) {
        if ((t & 31) == 0) {
            __syncwarp();
            for (int s2 = 0; s2 < 32; s2++) {
                int sl = __shfl_sync(FULL, len, s2);
                int sq = __shfl_sync(FULL, seq, s2);
                int tt = t + lane;
                float v = 0.0f;
                if (tt < sl) v = __ldg(h + (size_t)sq * T + (sl - 1 - tt));
                sx[w][lane][s2] = v;
            }
            __syncwarp();
        }
        int tc = t & 31;

        float xs[4][2];
#pragma unroll
        for (int n = 0; n < 4; n++)
#pragma unroll
            for (int u = 0; u < 2; u++)
                xs[n][u] = sx[w][tc][8 * n + 2 * tig + u];

        float d[2][4][4];
#pragma unroll
        for (int m = 0; m < 2; m++)
#pragma unroll
            for (int n = 0; n < 4; n++) {
                d[m][n][0] = fmaf(wih4[2 * m],     xs[n][0], b4[2 * m]);
                d[m][n][1] = fmaf(wih4[2 * m],     xs[n][1], b4[2 * m]);
                d[m][n][2] = fmaf(wih4[2 * m + 1], xs[n][0], b4[2 * m + 1]);
                d[m][n][3] = fmaf(wih4[2 * m + 1], xs[n][1], b4[2 * m + 1]);
            }

#pragma unroll
        for (int k = 0; k < 4; k++) {
            uint alo[2][4];
#pragma unroll
            for (int m = 0; m < 2; m++) {
                int r0 = 16 * m + gid, r1 = r0 + 8;
                int c0 = 8 * k + tig,  c1 = c0 + 4;
                alo[m][0] = __float_as_uint(sWlo[r0][c0]);
                alo[m][1] = __float_as_uint(sWlo[r1][c0]);
                alo[m][2] = __float_as_uint(sWlo[r0][c1]);
                alo[m][3] = __float_as_uint(sWlo[r1][c1]);
            }
#pragma unroll
            for (int n = 0; n < 4; n++) {
                float v0 = Hs[w][8 * k + tig][8 * n + gid];
                float v1 = Hs[w][8 * k + tig + 4][8 * n + gid];
                float h0 = trunc13(v0), h1 = trunc13(v1);
                uint b0hi = __float_as_uint(h0);
                uint b1hi = __float_as_uint(h1);
                uint b0lo = __float_as_uint(v0 - h0);
                uint b1lo = __float_as_uint(v1 - h1);
#pragma unroll
                for (int m = 0; m < 2; m++) {
                    mma_tf32(d[m][n][0], d[m][n][1], d[m][n][2], d[m][n][3],
                             awhi[m][k][0], awhi[m][k][1], awhi[m][k][2], awhi[m][k][3],
                             b0hi, b1hi);
                    mma_tf32(d[m][n][0], d[m][n][1], d[m][n][2], d[m][n][3],
                             awhi[m][k][0], awhi[m][k][1], awhi[m][k][2], awhi[m][k][3],
                             b0lo, b1lo);
                    mma_tf32(d[m][n][0], d[m][n][1], d[m][n][2], d[m][n][3],
                             alo[m][0], alo[m][1], alo[m][2], alo[m][3],
                             b0hi, b1hi);
                }
            }
        }

#pragma unroll
        for (int m = 0; m < 2; m++) {
            int r0 = 16 * m + gid, r1 = r0 + 8;
#pragma unroll
            for (int n = 0; n < 4; n++) {
                int c0 = 8 * n + 2 * tig, c1 = c0 + 1;
                float e0 = ex2f(d[m][n][0]);
                float e1 = ex2f(d[m][n][1]);
                float e2 = ex2f(d[m][n][2]);
                float e3 = ex2f(d[m][n][3]);
                float h0 = fmaf(-2.0f, rcpf(e0 + 1.0f), 1.0f);
                float h1 = fmaf(-2.0f, rcpf(e1 + 1.0f), 1.0f);
                float h2 = fmaf(-2.0f, rcpf(e2 + 1.0f), 1.0f);
                float h3 = fmaf(-2.0f, rcpf(e3 + 1.0f), 1.0f);
                if (t < lencol[n][0]) Hs[w][r0][c0] = h0;
                if (t < lencol[n][1]) Hs[w][r0][c1] = h1;
                if (t < lencol[n][0]) Hs[w][r1][c0] = h2;
                if (t < lencol[n][1]) Hs[w][r1][c1] = h3;
            }
        }
        __syncwarp();
    }

    __syncwarp();
    for (int s2 = 0; s2 < 32; s2++) {
        if ((blockIdx.x * NW + w) * 32 + s2 < NR) {
            int sq = __shfl_sync(FULL, seq, s2);
            g_emb[(size_t)sq * 32 + lane] = Hs[w][lane][s2];
        }
    }
}

// ---------------------------------------------------------------------------
// MLP head: warp-per-sample.
// ---------------------------------------------------------------------------
__global__ __launch_bounds__(256) void mlp_kernel(
    const float* __restrict__ W1, const float* __restrict__ b1,
    const float* __restrict__ W2, const float* __restrict__ b2,
    const float* __restrict__ W3, const float* __restrict__ b3,
    float* __restrict__ out, int N, int R)
{
    __shared__ float W1s[128 * 32];
    __shared__ float W2s[32 * 32];
    __shared__ float W3s[32 * 8];
    __shared__ float b1s[32], b2s[32], b3s[8];

    int tid = threadIdx.x;
    int RH  = R * 32;
    for (int i = tid; i < RH * 32; i += blockDim.x) W1s[i] = W1[i];
    for (int i = tid; i < 32 * 32; i += blockDim.x) W2s[i] = W2[i];
    for (int i = tid; i < 32 * R;  i += blockDim.x) W3s[i] = W3[i];
    if (tid < 32) { b1s[tid] = b1[tid]; b2s[tid] = b2[tid]; }
    if (tid < R)  b3s[tid] = b3[tid];
    __syncthreads();

    int warp = (int)((blockIdx.x * blockDim.x + tid) >> 5);
    int lane = tid & 31;
    if (warp >= N) return;

    float f0 = g_emb[((size_t)warp * R + 0) * 32 + lane];
    float f1 = g_emb[((size_t)warp * R + 1) * 32 + lane];
    float f2 = g_emb[((size_t)warp * R + 2) * 32 + lane];
    float f3 = g_emb[((size_t)warp * R + 3) * 32 + lane];

    float z = b1s[lane];
#pragma unroll
    for (int m = 0; m < 32; m++) {
        float fm = __shfl_sync(FULL, f0, m);
        z = fmaf(fm, W1s[m * 32 + lane], z);
    }
#pragma unroll
    for (int m = 0; m < 32; m++) {
        float fm = __shfl_sync(FULL, f1, m);
        z = fmaf(fm, W1s[(32 + m) * 32 + lane], z);
    }
#pragma unroll
    for (int m = 0; m < 32; m++) {
        float fm = __shfl_sync(FULL, f2, m);
        z = fmaf(fm, W1s[(64 + m) * 32 + lane], z);
    }
#pragma unroll
    for (int m = 0; m < 32; m++) {
        float fm = __shfl_sync(FULL, f3, m);
        z = fmaf(fm, W1s[(96 + m) * 32 + lane], z);
    }
    z = fmaxf(z, 0.0f);

    float z2 = b2s[lane];
#pragma unroll
    for (int m = 0; m < 32; m++) {
        float zm = __shfl_sync(FULL, z, m);
        z2 = fmaf(zm, W2s[m * 32 + lane], z2);
    }
    z2 = fmaxf(z2, 0.0f);

    for (int c = 0; c < R; c++) {
        float v = z2 * W3s[lane * R + c];
#pragma unroll
        for (int off = 16; off; off >>= 1) v += __shfl_xor_sync(FULL, v, off);
        if (lane == 0) out[(size_t)warp * R + c] = v + b3s[c];
    }
}

// ---------------------------------------------------------------------------
// Launcher. Inputs: h, l, W_ih, W_hh, b_ih, b_hh, W1, b1, W2, b2, W3, b3
// ---------------------------------------------------------------------------
extern "C" void kernel_launch(void* const* d_in, const int* in_sizes, int n_in,
                              void* d_out, int out_size)
{
    const float* h    = (const float*)d_in[0];
    const int*   l    = (const int*)  d_in[1];
    const float* W_ih = (const float*)d_in[2];
    const float* W_hh = (const float*)d_in[3];
    const float* b_ih = (const float*)d_in[4];
    const float* b_hh = (const float*)d_in[5];
    const float* W1   = (const float*)d_in[6];
    const float* b1   = (const float*)d_in[7];
    const float* W2   = (const float*)d_in[8];
    const float* b2   = (const float*)d_in[9];
    const float* W3   = (const float*)d_in[10];
    const float* b3   = (const float*)d_in[11];
    float* out = (float*)d_out;

    int NR = in_sizes[1];
    int T  = in_sizes[0] / NR;
    int R  = in_sizes[10] / 32;
    int N  = NR / R;

    zero_hist_kernel<<<1, 512>>>();
    hist_kernel<<<(NR + 255) / 256, 256>>>(l, NR);
    scan_kernel<<<1, 512>>>();
    scatter_kernel<<<(NR + 255) / 256, 256>>>(l, NR);

    int warps = (NR + 31) / 32;
    rnn_kernel<<<(warps + NW - 1) / NW, 32 * NW>>>(h, l, W_ih, W_hh, b_ih, b_hh, NR, T);

    mlp_kernel<<<(N + 7) / 8, 256>>>(W1, b1, W2, b2, W3, b3, out, N, R);
}

// round 6
// speedup vs baseline: 2.2336x; 1.0936x over previous
#include <cuda_runtime.h>
#include <cuda_bf16.h>
#include <math.h>

#define FULL 0xffffffffu
#define MAXNR 131072
#define NBINS 257

typedef unsigned int uint;
typedef unsigned short ushort;

// Scratch (device globals; no allocation allowed)
__device__ float g_emb[MAXNR * 32];
__device__ int   g_hist[NBINS];
__device__ int   g_binbase[NBINS];
__device__ int   g_perm[MAXNR];

// ---------------------------------------------------------------------------
// helpers
// ---------------------------------------------------------------------------
__device__ __forceinline__ float ex2f(float x) {
    float r; asm("ex2.approx.f32 %0, %1;" : "=f"(r) : "f"(x)); return r;
}
__device__ __forceinline__ float rcpf(float x) {
    float r; asm("rcp.approx.f32 %0, %1;" : "=f"(r) : "f"(x)); return r;
}
// pack two f32 into bf16x2: 'lo' -> low half, 'hi' -> high half
__device__ __forceinline__ uint packbf(float lo, float hi) {
    uint r; asm("cvt.rn.bf16x2.f32 %0, %1, %2;" : "=r"(r) : "f"(hi), "f"(lo)); return r;
}
__device__ __forceinline__ ushort bf16rn(float x) {
    ushort r; asm("cvt.rn.bf16.f32 %0, %1;" : "=h"(r) : "f"(x)); return r;
}
__device__ __forceinline__ float bf2f(ushort u) {
    return __uint_as_float(((uint)u) << 16);
}
__device__ __forceinline__ void mma_bf16(
    float& d0, float& d1, float& d2, float& d3,
    uint a0, uint a1, uint a2, uint a3, uint b0, uint b1)
{
    asm("mma.sync.aligned.m16n8k16.row.col.f32.bf16.bf16.f32 "
        "{%0,%1,%2,%3}, {%4,%5,%6,%7}, {%8,%9}, {%0,%1,%2,%3};"
        : "+f"(d0), "+f"(d1), "+f"(d2), "+f"(d3)
        : "r"(a0), "r"(a1), "r"(a2), "r"(a3), "r"(b0), "r"(b1));
}

// ---------------------------------------------------------------------------
// Counting sort by length (descending)
// ---------------------------------------------------------------------------
__global__ void zero_hist_kernel() {
    int i = threadIdx.x;
    if (i < NBINS) g_hist[i] = 0;
}

__global__ void hist_kernel(const int* __restrict__ l, int NR) {
    __shared__ int sh[NBINS];
    for (int i = threadIdx.x; i < NBINS; i += blockDim.x) sh[i] = 0;
    __syncthreads();
    int i = blockIdx.x * blockDim.x + threadIdx.x;
    if (i < NR) atomicAdd(&sh[l[i]], 1);
    __syncthreads();
    for (int i2 = threadIdx.x; i2 < NBINS; i2 += blockDim.x)
        if (sh[i2]) atomicAdd(&g_hist[i2], sh[i2]);
}

__global__ void scan_kernel() {   // 1 block, 512 threads
    __shared__ int s[512];
    int tid = threadIdx.x;
    int hv = (tid < NBINS) ? g_hist[256 - tid] : 0;
    s[tid] = hv;
    __syncthreads();
    for (int off = 1; off < 512; off <<= 1) {
        int v = (tid >= off) ? s[tid - off] : 0;
        __syncthreads();
        s[tid] += v;
        __syncthreads();
    }
    if (tid < NBINS) g_binbase[256 - tid] = s[tid] - hv;
}

__global__ void scatter_kernel(const int* __restrict__ l, int NR) {
    __shared__ int scount[NBINS];
    __shared__ int sbase[NBINS];
    for (int i = threadIdx.x; i < NBINS; i += blockDim.x) scount[i] = 0;
    __syncthreads();
    int i = blockIdx.x * blockDim.x + threadIdx.x;
    int len = 0, local = 0;
    if (i < NR) {
        len = l[i];
        local = atomicAdd(&scount[len], 1);
    }
    __syncthreads();
    for (int b = threadIdx.x; b < NBINS; b += blockDim.x)
        sbase[b] = scount[b] ? atomicAdd(&g_binbase[b], scount[b]) : 0;
    __syncthreads();
    if (i < NR) g_perm[sbase[len] + local] = i;
}

// ---------------------------------------------------------------------------
// RNN via bf16-split tensor cores (mma.sync m16n8k16, 3-term split:
// Whi*Hhi + Whi*Hlo + Wlo*Hhi). Per warp: 32 sorted sequences; per step a
// 32x32x32 GEMM a = S*(W@H + wih*x + b), then h = 1 - 2*rcp(ex2(a)+1).
// S = 2*log2(e) pre-folded. H kept in shared as two bf16 planes [s][j].
// ---------------------------------------------------------------------------
#define NW 4   // warps per block

__global__ __launch_bounds__(32 * NW) void rnn_kernel(
    const float* __restrict__ h,
    const int*   __restrict__ l,
    const float* __restrict__ W_ih,
    const float* __restrict__ W_hh,
    const float* __restrict__ b_ih,
    const float* __restrict__ b_hh,
    int NR, int T)
{
    __shared__ float  sWhi[32][33];
    __shared__ float  sWlo[32][33];
    __shared__ float  swihS[32];
    __shared__ float  sbS[32];
    __shared__ ushort Hhi[NW][32][40];   // bf16 hi plane, [s][j]
    __shared__ ushort Hlo[NW][32][40];   // bf16 lo plane, [s][j]
    __shared__ float  sx[NW][32][33];    // staged inputs [t&31][s]

    const float S = 2.8853900817779268f;   // 2*log2(e)
    int tid  = threadIdx.x;
    int w    = tid >> 5;
    int lane = tid & 31;
    int gid  = lane >> 2;
    int tig  = lane & 3;

    // stage scaled + truncation-split weights
    for (int idx = tid; idx < 1024; idx += 32 * NW) {
        float ws  = S * W_hh[idx];
        float whi = __uint_as_float(__float_as_uint(ws) & 0xFFFF0000u);
        sWhi[idx >> 5][idx & 31] = whi;
        sWlo[idx >> 5][idx & 31] = ws - whi;
    }
    if (tid < 32) {
        swihS[tid] = S * W_ih[tid];
        sbS[tid]   = S * (b_ih[tid] + b_hh[tid]);
    }
    __syncthreads();

    // A fragments in registers: [m-tile][k-tile][reg], bf16x2 packed
    uint awhi[2][2][4], awlo[2][2][4];
#pragma unroll
    for (int m = 0; m < 2; m++)
#pragma unroll
        for (int kt = 0; kt < 2; kt++) {
            int r0 = 16 * m + gid, r1 = r0 + 8;
            int c0 = 16 * kt + 2 * tig, c2 = c0 + 8;
            awhi[m][kt][0] = packbf(sWhi[r0][c0], sWhi[r0][c0 + 1]);
            awhi[m][kt][1] = packbf(sWhi[r1][c0], sWhi[r1][c0 + 1]);
            awhi[m][kt][2] = packbf(sWhi[r0][c2], sWhi[r0][c2 + 1]);
            awhi[m][kt][3] = packbf(sWhi[r1][c2], sWhi[r1][c2 + 1]);
            awlo[m][kt][0] = packbf(sWlo[r0][c0], sWlo[r0][c0 + 1]);
            awlo[m][kt][1] = packbf(sWlo[r1][c0], sWlo[r1][c0 + 1]);
            awlo[m][kt][2] = packbf(sWlo[r0][c2], sWlo[r0][c2 + 1]);
            awlo[m][kt][3] = packbf(sWlo[r1][c2], sWlo[r1][c2 + 1]);
        }

    float wih4[4], b4[4];
#pragma unroll
    for (int q = 0; q < 4; q++) {
        wih4[q] = swihS[gid + 8 * q];
        b4[q]   = sbS[gid + 8 * q];
    }

    int gi  = (blockIdx.x * NW + w) * 32 + lane;
    int seq = (gi < NR) ? g_perm[gi] : 0;
    int len = (gi < NR) ? l[seq] : 0;
    int maxlen = __reduce_max_sync(FULL, len);

    int lencol[4][2];
#pragma unroll
    for (int n = 0; n < 4; n++)
#pragma unroll
        for (int u = 0; u < 2; u++)
            lencol[n][u] = __shfl_sync(FULL, len, 8 * n + 2 * tig + u);

    // zero hidden planes (incl. padding)
    {
        uint* p0 = (uint*)&Hhi[w][0][0];
        uint* p1 = (uint*)&Hlo[w][0][0];
        for (int q = lane; q < 32 * 20; q += 32) { p0[q] = 0; p1[q] = 0; }
    }
    __syncwarp();

    ushort* HhiW = &Hhi[w][0][0];
    ushort* HloW = &Hlo[w][0][0];

    for (int t = 0; t < maxlen; t++) {
        if ((t & 31) == 0) {
            __syncwarp();
            for (int s2 = 0; s2 < 32; s2++) {
                int sl = __shfl_sync(FULL, len, s2);
                int sq = __shfl_sync(FULL, seq, s2);
                int tt = t + lane;
                float v = 0.0f;
                if (tt < sl) v = __ldg(h + (size_t)sq * T + (sl - 1 - tt));
                sx[w][lane][s2] = v;
            }
            __syncwarp();
        }
        int tc = t & 31;

        // init accumulators with S*(wih*x + bias)
        float d[2][4][4];
#pragma unroll
        for (int n = 0; n < 4; n++) {
            float x0 = sx[w][tc][8 * n + 2 * tig];
            float x1 = sx[w][tc][8 * n + 2 * tig + 1];
#pragma unroll
            for (int m = 0; m < 2; m++) {
                d[m][n][0] = fmaf(wih4[2 * m],     x0, b4[2 * m]);
                d[m][n][1] = fmaf(wih4[2 * m],     x1, b4[2 * m]);
                d[m][n][2] = fmaf(wih4[2 * m + 1], x0, b4[2 * m + 1]);
                d[m][n][3] = fmaf(wih4[2 * m + 1], x1, b4[2 * m + 1]);
            }
        }

        // GEMM: 2 k-tiles x 4 n-tiles x 2 m-tiles x 3 split-terms
#pragma unroll
        for (int kt = 0; kt < 2; kt++) {
#pragma unroll
            for (int nt = 0; nt < 4; nt++) {
                int base = (8 * nt + gid) * 40 + 16 * kt + 2 * tig;
                uint bhi0 = *(const uint*)(HhiW + base);
                uint bhi1 = *(const uint*)(HhiW + base + 8);
                uint blo0 = *(const uint*)(HloW + base);
                uint blo1 = *(const uint*)(HloW + base + 8);
#pragma unroll
                for (int m = 0; m < 2; m++) {
                    mma_bf16(d[m][nt][0], d[m][nt][1], d[m][nt][2], d[m][nt][3],
                             awhi[m][kt][0], awhi[m][kt][1], awhi[m][kt][2], awhi[m][kt][3],
                             bhi0, bhi1);
                    mma_bf16(d[m][nt][0], d[m][nt][1], d[m][nt][2], d[m][nt][3],
                             awhi[m][kt][0], awhi[m][kt][1], awhi[m][kt][2], awhi[m][kt][3],
                             blo0, blo1);
                    mma_bf16(d[m][nt][0], d[m][nt][1], d[m][nt][2], d[m][nt][3],
                             awlo[m][kt][0], awlo[m][kt][1], awlo[m][kt][2], awlo[m][kt][3],
                             bhi0, bhi1);
                }
            }
        }

        // epilogue: tanh + bf16 split + predicated store to H planes
#pragma unroll
        for (int m = 0; m < 2; m++) {
            int r0 = 16 * m + gid, r1 = r0 + 8;
#pragma unroll
            for (int n = 0; n < 4; n++) {
                int c0 = 8 * n + 2 * tig, c1 = c0 + 1;
#pragma unroll
                for (int v = 0; v < 4; v++) {
                    int rr = (v < 2) ? r0 : r1;
                    int cc = (v & 1) ? c1 : c0;
                    int lc = lencol[n][v & 1];
                    float e  = ex2f(d[m][n][v]);
                    float hv = fmaf(-2.0f, rcpf(e + 1.0f), 1.0f);
                    uint  hb = __float_as_uint(hv);
                    float hif = __uint_as_float(hb & 0xFFFF0000u);
                    ushort hi16 = (ushort)(hb >> 16);
                    ushort lo16 = bf16rn(hv - hif);
                    if (t < lc) {
                        HhiW[cc * 40 + rr] = hi16;
                        HloW[cc * 40 + rr] = lo16;
                    }
                }
            }
        }
        __syncwarp();
    }

    // write final hidden states (hi+lo reconstruction) to g_emb
    __syncwarp();
    for (int s2 = 0; s2 < 32; s2++) {
        if ((blockIdx.x * NW + w) * 32 + s2 < NR) {
            int sq = __shfl_sync(FULL, seq, s2);
            float hv = bf2f(Hhi[w][s2][lane]) + bf2f(Hlo[w][s2][lane]);
            g_emb[(size_t)sq * 32 + lane] = hv;
        }
    }
}

// ---------------------------------------------------------------------------
// MLP head: warp-per-sample.
// ---------------------------------------------------------------------------
__global__ __launch_bounds__(256) void mlp_kernel(
    const float* __restrict__ W1, const float* __restrict__ b1,
    const float* __restrict__ W2, const float* __restrict__ b2,
    const float* __restrict__ W3, const float* __restrict__ b3,
    float* __restrict__ out, int N, int R)
{
    __shared__ float W1s[128 * 32];
    __shared__ float W2s[32 * 32];
    __shared__ float W3s[32 * 8];
    __shared__ float b1s[32], b2s[32], b3s[8];

    int tid = threadIdx.x;
    int RH  = R * 32;
    for (int i = tid; i < RH * 32; i += blockDim.x) W1s[i] = W1[i];
    for (int i = tid; i < 32 * 32; i += blockDim.x) W2s[i] = W2[i];
    for (int i = tid; i < 32 * R;  i += blockDim.x) W3s[i] = W3[i];
    if (tid < 32) { b1s[tid] = b1[tid]; b2s[tid] = b2[tid]; }
    if (tid < R)  b3s[tid] = b3[tid];
    __syncthreads();

    int warp = (int)((blockIdx.x * blockDim.x + tid) >> 5);
    int lane = tid & 31;
    if (warp >= N) return;

    float f0 = g_emb[((size_t)warp * R + 0) * 32 + lane];
    float f1 = g_emb[((size_t)warp * R + 1) * 32 + lane];
    float f2 = g_emb[((size_t)warp * R + 2) * 32 + lane];
    float f3 = g_emb[((size_t)warp * R + 3) * 32 + lane];

    float z = b1s[lane];
#pragma unroll
    for (int m = 0; m < 32; m++) {
        float fm = __shfl_sync(FULL, f0, m);
        z = fmaf(fm, W1s[m * 32 + lane], z);
    }
#pragma unroll
    for (int m = 0; m < 32; m++) {
        float fm = __shfl_sync(FULL, f1, m);
        z = fmaf(fm, W1s[(32 + m) * 32 + lane], z);
    }
#pragma unroll
    for (int m = 0; m < 32; m++) {
        float fm = __shfl_sync(FULL, f2, m);
        z = fmaf(fm, W1s[(64 + m) * 32 + lane], z);
    }
#pragma unroll
    for (int m = 0; m < 32; m++) {
        float fm = __shfl_sync(FULL, f3, m);
        z = fmaf(fm, W1s[(96 + m) * 32 + lane], z);
    }
    z = fmaxf(z, 0.0f);

    float z2 = b2s[lane];
#pragma unroll
    for (int m = 0; m < 32; m++) {
        float zm = __shfl_sync(FULL, z, m);
        z2 = fmaf(zm, W2s[m * 32 + lane], z2);
    }
    z2 = fmaxf(z2, 0.0f);

    for (int c = 0; c < R; c++) {
        float v = z2 * W3s[lane * R + c];
#pragma unroll
        for (int off = 16; off; off >>= 1) v += __shfl_xor_sync(FULL, v, off);
        if (lane == 0) out[(size_t)warp * R + c] = v + b3s[c];
    }
}

// ---------------------------------------------------------------------------
// Launcher. Inputs: h, l, W_ih, W_hh, b_ih, b_hh, W1, b1, W2, b2, W3, b3
// ---------------------------------------------------------------------------
extern "C" void kernel_launch(void* const* d_in, const int* in_sizes, int n_in,
                              void* d_out, int out_size)
{
    const float* h    = (const float*)d_in[0];
    const int*   l    = (const int*)  d_in[1];
    const float* W_ih = (const float*)d_in[2];
    const float* W_hh = (const float*)d_in[3];
    const float* b_ih = (const float*)d_in[4];
    const float* b_hh = (const float*)d_in[5];
    const float* W1   = (const float*)d_in[6];
    const float* b1   = (const float*)d_in[7];
    const float* W2   = (const float*)d_in[8];
    const float* b2   = (const float*)d_in[9];
    const float* W3   = (const float*)d_in[10];
    const float* b3   = (const float*)d_in[11];
    float* out = (float*)d_out;

    int NR = in_sizes[1];
    int T  = in_sizes[0] / NR;
    int R  = in_sizes[10] / 32;
    int N  = NR / R;

    zero_hist_kernel<<<1, 512>>>();
    hist_kernel<<<(NR + 255) / 256, 256>>>(l, NR);
    scan_kernel<<<1, 512>>>();
    scatter_kernel<<<(NR + 255) / 256, 256>>>(l, NR);

    int warps = (NR + 31) / 32;
    rnn_kernel<<<(warps + NW - 1) / NW, 32 * NW>>>(h, l, W_ih, W_hh, b_ih, b_hh, NR, T);

    mlp_kernel<<<(N + 7) / 8, 256>>>(W1, b1, W2, b2, W3, b3, out, N, R);
}

// round 7
// speedup vs baseline: 3.6113x; 1.6168x over previous
#include <cuda_runtime.h>
#include <cuda_bf16.h>
#include <math.h>

#define FULL 0xffffffffu
#define MAXNR 131072
#define NBINS 257

typedef unsigned int uint;
typedef unsigned short ushort;

// Scratch (device globals; no allocation allowed)
__device__ float g_emb[MAXNR * 32];
__device__ int   g_hist[NBINS];
__device__ int   g_binbase[NBINS];
__device__ int   g_perm[MAXNR];

// ---------------------------------------------------------------------------
// helpers
// ---------------------------------------------------------------------------
__device__ __forceinline__ float tanhapx(float x) {
    float r; asm("tanh.approx.f32 %0, %1;" : "=f"(r) : "f"(x)); return r;
}
// pack two f32 into bf16x2 (lo -> low half, hi -> high half)
__device__ __forceinline__ uint packbf(float lo, float hi) {
    uint r; asm("cvt.rn.bf16x2.f32 %0, %1, %2;" : "=r"(r) : "f"(hi), "f"(lo)); return r;
}
__device__ __forceinline__ void mma_bf16(
    float& d0, float& d1, float& d2, float& d3,
    uint a0, uint a1, uint a2, uint a3, uint b0, uint b1)
{
    asm("mma.sync.aligned.m16n8k16.row.col.f32.bf16.bf16.f32 "
        "{%0,%1,%2,%3}, {%4,%5,%6,%7}, {%8,%9}, {%0,%1,%2,%3};"
        : "+f"(d0), "+f"(d1), "+f"(d2), "+f"(d3)
        : "r"(a0), "r"(a1), "r"(a2), "r"(a3), "r"(b0), "r"(b1));
}
__device__ __forceinline__ void ldsm4t(uint& d0, uint& d1, uint& d2, uint& d3, uint saddr) {
    asm volatile("ldmatrix.sync.aligned.m8n8.x4.trans.shared.b16 {%0,%1,%2,%3}, [%4];"
        : "=r"(d0), "=r"(d1), "=r"(d2), "=r"(d3) : "r"(saddr));
}

// ---------------------------------------------------------------------------
// Counting sort by length (descending)
// ---------------------------------------------------------------------------
__global__ void zero_hist_kernel() {
    int i = threadIdx.x;
    if (i < NBINS) g_hist[i] = 0;
}

__global__ void hist_kernel(const int* __restrict__ l, int NR) {
    __shared__ int sh[NBINS];
    for (int i = threadIdx.x; i < NBINS; i += blockDim.x) sh[i] = 0;
    __syncthreads();
    int i = blockIdx.x * blockDim.x + threadIdx.x;
    if (i < NR) atomicAdd(&sh[l[i]], 1);
    __syncthreads();
    for (int i2 = threadIdx.x; i2 < NBINS; i2 += blockDim.x)
        if (sh[i2]) atomicAdd(&g_hist[i2], sh[i2]);
}

__global__ void scan_kernel() {   // 1 block, 512 threads
    __shared__ int s[512];
    int tid = threadIdx.x;
    int hv = (tid < NBINS) ? g_hist[256 - tid] : 0;
    s[tid] = hv;
    __syncthreads();
    for (int off = 1; off < 512; off <<= 1) {
        int v = (tid >= off) ? s[tid - off] : 0;
        __syncthreads();
        s[tid] += v;
        __syncthreads();
    }
    if (tid < NBINS) g_binbase[256 - tid] = s[tid] - hv;
}

__global__ void scatter_kernel(const int* __restrict__ l, int NR) {
    __shared__ int scount[NBINS];
    __shared__ int sbase[NBINS];
    for (int i = threadIdx.x; i < NBINS; i += blockDim.x) scount[i] = 0;
    __syncthreads();
    int i = blockIdx.x * blockDim.x + threadIdx.x;
    int len = 0, local = 0;
    if (i < NR) {
        len = l[i];
        local = atomicAdd(&scount[len], 1);
    }
    __syncthreads();
    for (int b = threadIdx.x; b < NBINS; b += blockDim.x)
        sbase[b] = scount[b] ? atomicAdd(&g_binbase[b], scount[b]) : 0;
    __syncthreads();
    if (i < NR) g_perm[sbase[len] + local] = i;
}

// ---------------------------------------------------------------------------
// RNN via bf16-split tensor cores (m16n8k16; Whi*Hhi + Whi*Hlo + Wlo*Hhi).
// H planes in [j][s] layout (pad 40 shorts): B fragments via ldmatrix.trans,
// epilogue stores as packed bf16x2 STS.32. Finished columns keep evolving in
// smem (results discarded); per-thread `hold` registers snapshot the final h.
// tanh via MUFU.TANH (tanh.approx.f32).
// ---------------------------------------------------------------------------
#define NW 4   // warps per block
#define HP 40  // H plane row pad (shorts)

__global__ __launch_bounds__(32 * NW, 3) void rnn_kernel(
    const float* __restrict__ h,
    const int*   __restrict__ l,
    const float* __restrict__ W_ih,
    const float* __restrict__ W_hh,
    const float* __restrict__ b_ih,
    const float* __restrict__ b_hh,
    int NR, int T)
{
    __shared__ float  sWhi[32][33];
    __shared__ float  sWlo[32][33];
    __shared__ float  swih[32];
    __shared__ float  sb[32];
    __shared__ __align__(16) ushort Hhi[NW][32][HP];   // [j][s]
    __shared__ __align__(16) ushort Hlo[NW][32][HP];   // [j][s]
    __shared__ __align__(16) float  sx[NW][32][34];    // staged inputs [t&31][s]

    int tid  = threadIdx.x;
    int w    = tid >> 5;
    int lane = tid & 31;
    int gid  = lane >> 2;
    int tig  = lane & 3;

    // stage truncation-split weights (no scale: tanh.approx takes plain arg)
    for (int idx = tid; idx < 1024; idx += 32 * NW) {
        float ws  = W_hh[idx];
        float whi = __uint_as_float(__float_as_uint(ws) & 0xFFFF0000u);
        sWhi[idx >> 5][idx & 31] = whi;
        sWlo[idx >> 5][idx & 31] = ws - whi;
    }
    if (tid < 32) {
        swih[tid] = W_ih[tid];
        sb[tid]   = b_ih[tid] + b_hh[tid];
    }
    __syncthreads();

    // A fragments in registers: [m-tile][k-tile][reg], bf16x2 packed
    uint awhi[2][2][4], awlo[2][2][4];
#pragma unroll
    for (int m = 0; m < 2; m++)
#pragma unroll
        for (int kt = 0; kt < 2; kt++) {
            int r0 = 16 * m + gid, r1 = r0 + 8;
            int c0 = 16 * kt + 2 * tig, c2 = c0 + 8;
            awhi[m][kt][0] = packbf(sWhi[r0][c0], sWhi[r0][c0 + 1]);
            awhi[m][kt][1] = packbf(sWhi[r1][c0], sWhi[r1][c0 + 1]);
            awhi[m][kt][2] = packbf(sWhi[r0][c2], sWhi[r0][c2 + 1]);
            awhi[m][kt][3] = packbf(sWhi[r1][c2], sWhi[r1][c2 + 1]);
            awlo[m][kt][0] = packbf(sWlo[r0][c0], sWlo[r0][c0 + 1]);
            awlo[m][kt][1] = packbf(sWlo[r1][c0], sWlo[r1][c0 + 1]);
            awlo[m][kt][2] = packbf(sWlo[r0][c2], sWlo[r0][c2 + 1]);
            awlo[m][kt][3] = packbf(sWlo[r1][c2], sWlo[r1][c2 + 1]);
        }

    float wih4[4], b4[4];
#pragma unroll
    for (int q = 0; q < 4; q++) {
        wih4[q] = swih[gid + 8 * q];
        b4[q]   = sb[gid + 8 * q];
    }

    int gi  = (blockIdx.x * NW + w) * 32 + lane;
    int seq = (gi < NR) ? g_perm[gi] : 0;
    int len = (gi < NR) ? l[seq] : 0;
    int maxlen = __reduce_max_sync(FULL, len);

    int lencol[4][2];
#pragma unroll
    for (int n = 0; n < 4; n++)
#pragma unroll
        for (int u = 0; u < 2; u++)
            lencol[n][u] = __shfl_sync(FULL, len, 8 * n + 2 * tig + u);

    // zero hidden planes
    {
        uint* p0 = (uint*)&Hhi[w][0][0];
        uint* p1 = (uint*)&Hlo[w][0][0];
        for (int q = lane; q < 32 * HP / 2; q += 32) { p0[q] = 0; p1[q] = 0; }
    }
    __syncwarp();

    // ldmatrix per-lane base addresses (trans: 4 tiles = (j0,s0),(j0+8,s0),(j0,s0+8),(j0+8,s0+8))
    int m8 = lane >> 3, r8 = lane & 7;
    uint lanoff = (uint)(((8 * (m8 & 1) + r8) * HP + 8 * (m8 >> 1)) * 2);
    uint hbase = (uint)__cvta_generic_to_shared(&Hhi[w][0][0]) + lanoff;
    uint lbase = (uint)__cvta_generic_to_shared(&Hlo[w][0][0]) + lanoff;

    ushort* HhiW = &Hhi[w][0][0];
    ushort* HloW = &Hlo[w][0][0];

    // snapshot registers: thread owns h for rows {16m+gid, 16m+8+gid}, cols {8n+2tig,+1}
    float hold[2][4][4];
#pragma unroll
    for (int m = 0; m < 2; m++)
#pragma unroll
        for (int n = 0; n < 4; n++)
#pragma unroll
            for (int v = 0; v < 4; v++) hold[m][n][v] = 0.0f;

    for (int t = 0; t < maxlen; t++) {
        if ((t & 31) == 0) {
            for (int s2 = 0; s2 < 32; s2++) {
                int sl = __shfl_sync(FULL, len, s2);
                int sq = __shfl_sync(FULL, seq, s2);
                int tt = t + lane;
                float v = 0.0f;
                if (tt < sl) v = __ldg(h + (size_t)sq * T + (sl - 1 - tt));
                sx[w][lane][s2] = v;
            }
            __syncwarp();
        }
        int tc = t & 31;

        // init accumulators with wih*x + bias
        float d[2][4][4];
#pragma unroll
        for (int n = 0; n < 4; n++) {
            float2 xv = *(const float2*)&sx[w][tc][8 * n + 2 * tig];
#pragma unroll
            for (int m = 0; m < 2; m++) {
                d[m][n][0] = fmaf(wih4[2 * m],     xv.x, b4[2 * m]);
                d[m][n][1] = fmaf(wih4[2 * m],     xv.y, b4[2 * m]);
                d[m][n][2] = fmaf(wih4[2 * m + 1], xv.x, b4[2 * m + 1]);
                d[m][n][3] = fmaf(wih4[2 * m + 1], xv.y, b4[2 * m + 1]);
            }
        }

        // GEMM: per (kt, nt-pair): 2 ldmatrix.x4.trans, then 3-term MMAs
#pragma unroll
        for (int kt = 0; kt < 2; kt++) {
#pragma unroll
            for (int ntp = 0; ntp < 2; ntp++) {
                uint off = (uint)((16 * kt * HP + 16 * ntp) * 2);
                uint bh0, bh1, bh2, bh3, bl0, bl1, bl2, bl3;
                ldsm4t(bh0, bh1, bh2, bh3, hbase + off);
                ldsm4t(bl0, bl1, bl2, bl3, lbase + off);
                int n0 = 2 * ntp, n1 = n0 + 1;
#pragma unroll
                for (int m = 0; m < 2; m++) {
                    mma_bf16(d[m][n0][0], d[m][n0][1], d[m][n0][2], d[m][n0][3],
                             awhi[m][kt][0], awhi[m][kt][1], awhi[m][kt][2], awhi[m][kt][3],
                             bh0, bh1);
                    mma_bf16(d[m][n0][0], d[m][n0][1], d[m][n0][2], d[m][n0][3],
                             awhi[m][kt][0], awhi[m][kt][1], awhi[m][kt][2], awhi[m][kt][3],
                             bl0, bl1);
                    mma_bf16(d[m][n0][0], d[m][n0][1], d[m][n0][2], d[m][n0][3],
                             awlo[m][kt][0], awlo[m][kt][1], awlo[m][kt][2], awlo[m][kt][3],
                             bh0, bh1);
                    mma_bf16(d[m][n1][0], d[m][n1][1], d[m][n1][2], d[m][n1][3],
                             awhi[m][kt][0], awhi[m][kt][1], awhi[m][kt][2], awhi[m][kt][3],
                             bh2, bh3);
                    mma_bf16(d[m][n1][0], d[m][n1][1], d[m][n1][2], d[m][n1][3],
                             awhi[m][kt][0], awhi[m][kt][1], awhi[m][kt][2], awhi[m][kt][3],
                             bl2, bl3);
                    mma_bf16(d[m][n1][0], d[m][n1][1], d[m][n1][2], d[m][n1][3],
                             awlo[m][kt][0], awlo[m][kt][1], awlo[m][kt][2], awlo[m][kt][3],
                             bh2, bh3);
                }
            }
        }
        __syncwarp();   // all B reads done before plane overwrite

        // epilogue: tanh, snapshot-select, bf16 split, packed stores
#pragma unroll
        for (int m = 0; m < 2; m++) {
            int r0 = 16 * m + gid, r1 = r0 + 8;
#pragma unroll
            for (int n = 0; n < 4; n++) {
                int c0 = 8 * n + 2 * tig;
                float nh0 = tanhapx(d[m][n][0]);
                float nh1 = tanhapx(d[m][n][1]);
                float nh2 = tanhapx(d[m][n][2]);
                float nh3 = tanhapx(d[m][n][3]);
                bool p0 = t < lencol[n][0], p1 = t < lencol[n][1];
                hold[m][n][0] = p0 ? nh0 : hold[m][n][0];
                hold[m][n][1] = p1 ? nh1 : hold[m][n][1];
                hold[m][n][2] = p0 ? nh2 : hold[m][n][2];
                hold[m][n][3] = p1 ? nh3 : hold[m][n][3];

                uint hiA = packbf(nh0, nh1);
                float hA0 = __uint_as_float(hiA << 16);
                float hA1 = __uint_as_float(hiA & 0xFFFF0000u);
                uint loA = packbf(nh0 - hA0, nh1 - hA1);
                *(uint*)&HhiW[r0 * HP + c0] = hiA;
                *(uint*)&HloW[r0 * HP + c0] = loA;

                uint hiB = packbf(nh2, nh3);
                float hB0 = __uint_as_float(hiB << 16);
                float hB1 = __uint_as_float(hiB & 0xFFFF0000u);
                uint loB = packbf(nh2 - hB0, nh3 - hB1);
                *(uint*)&HhiW[r1 * HP + c0] = hiB;
                *(uint*)&HloW[r1 * HP + c0] = loB;
            }
        }
        __syncwarp();
    }

    // stage snapshots to shared [s][j], then coalesced output
    __syncwarp();
#pragma unroll
    for (int m = 0; m < 2; m++) {
        int r0 = 16 * m + gid, r1 = r0 + 8;
#pragma unroll
        for (int n = 0; n < 4; n++) {
            int c0 = 8 * n + 2 * tig;
            sx[w][c0][r0]     = hold[m][n][0];
            sx[w][c0 + 1][r0] = hold[m][n][1];
            sx[w][c0][r1]     = hold[m][n][2];
            sx[w][c0 + 1][r1] = hold[m][n][3];
        }
    }
    __syncwarp();
    for (int s2 = 0; s2 < 32; s2++) {
        if ((blockIdx.x * NW + w) * 32 + s2 < NR) {
            int sq = __shfl_sync(FULL, seq, s2);
            g_emb[(size_t)sq * 32 + lane] = sx[w][s2][lane];
        }
    }
}

// ---------------------------------------------------------------------------
// MLP head: warp-per-sample.
// ---------------------------------------------------------------------------
__global__ __launch_bounds__(256) void mlp_kernel(
    const float* __restrict__ W1, const float* __restrict__ b1,
    const float* __restrict__ W2, const float* __restrict__ b2,
    const float* __restrict__ W3, const float* __restrict__ b3,
    float* __restrict__ out, int N, int R)
{
    __shared__ float W1s[128 * 32];
    __shared__ float W2s[32 * 32];
    __shared__ float W3s[32 * 8];
    __shared__ float b1s[32], b2s[32], b3s[8];

    int tid = threadIdx.x;
    int RH  = R * 32;
    for (int i = tid; i < RH * 32; i += blockDim.x) W1s[i] = W1[i];
    for (int i = tid; i < 32 * 32; i += blockDim.x) W2s[i] = W2[i];
    for (int i = tid; i < 32 * R;  i += blockDim.x) W3s[i] = W3[i];
    if (tid < 32) { b1s[tid] = b1[tid]; b2s[tid] = b2[tid]; }
    if (tid < R)  b3s[tid] = b3[tid];
    __syncthreads();

    int warp = (int)((blockIdx.x * blockDim.x + tid) >> 5);
    int lane = tid & 31;
    if (warp >= N) return;

    float f0 = g_emb[((size_t)warp * R + 0) * 32 + lane];
    float f1 = g_emb[((size_t)warp * R + 1) * 32 + lane];
    float f2 = g_emb[((size_t)warp * R + 2) * 32 + lane];
    float f3 = g_emb[((size_t)warp * R + 3) * 32 + lane];

    float z = b1s[lane];
#pragma unroll
    for (int m = 0; m < 32; m++) {
        float fm = __shfl_sync(FULL, f0, m);
        z = fmaf(fm, W1s[m * 32 + lane], z);
    }
#pragma unroll
    for (int m = 0; m < 32; m++) {
        float fm = __shfl_sync(FULL, f1, m);
        z = fmaf(fm, W1s[(32 + m) * 32 + lane], z);
    }
#pragma unroll
    for (int m = 0; m < 32; m++) {
        float fm = __shfl_sync(FULL, f2, m);
        z = fmaf(fm, W1s[(64 + m) * 32 + lane], z);
    }
#pragma unroll
    for (int m = 0; m < 32; m++) {
        float fm = __shfl_sync(FULL, f3, m);
        z = fmaf(fm, W1s[(96 + m) * 32 + lane], z);
    }
    z = fmaxf(z, 0.0f);

    float z2 = b2s[lane];
#pragma unroll
    for (int m = 0; m < 32; m++) {
        float zm = __shfl_sync(FULL, z, m);
        z2 = fmaf(zm, W2s[m * 32 + lane], z2);
    }
    z2 = fmaxf(z2, 0.0f);

    for (int c = 0; c < R; c++) {
        float v = z2 * W3s[lane * R + c];
#pragma unroll
        for (int off = 16; off; off >>= 1) v += __shfl_xor_sync(FULL, v, off);
        if (lane == 0) out[(size_t)warp * R + c] = v + b3s[c];
    }
}

// ---------------------------------------------------------------------------
// Launcher. Inputs: h, l, W_ih, W_hh, b_ih, b_hh, W1, b1, W2, b2, W3, b3
// ---------------------------------------------------------------------------
extern "C" void kernel_launch(void* const* d_in, const int* in_sizes, int n_in,
                              void* d_out, int out_size)
{
    const float* h    = (const float*)d_in[0];
    const int*   l    = (const int*)  d_in[1];
    const float* W_ih = (const float*)d_in[2];
    const float* W_hh = (const float*)d_in[3];
    const float* b_ih = (const float*)d_in[4];
    const float* b_hh = (const float*)d_in[5];
    const float* W1   = (const float*)d_in[6];
    const float* b1   = (const float*)d_in[7];
    const float* W2   = (const float*)d_in[8];
    const float* b2   = (const float*)d_in[9];
    const float* W3   = (const float*)d_in[10];
    const float* b3   = (const float*)d_in[11];
    float* out = (float*)d_out;

    int NR = in_sizes[1];
    int T  = in_sizes[0] / NR;
    int R  = in_sizes[10] / 32;
    int N  = NR / R;

    zero_hist_kernel<<<1, 512>>>();
    hist_kernel<<<(NR + 255) / 256, 256>>>(l, NR);
    scan_kernel<<<1, 512>>>();
    scatter_kernel<<<(NR + 255) / 256, 256>>>(l, NR);

    int warps = (NR + 31) / 32;
    rnn_kernel<<<(warps + NW - 1) / NW, 32 * NW>>>(h, l, W_ih, W_hh, b_ih, b_hh, NR, T);

    mlp_kernel<<<(N + 7) / 8, 256>>>(W1, b1, W2, b2, W3, b3, out, N, R);
}